// round 5
// baseline (speedup 1.0000x reference)
#include <cuda_runtime.h>
#include <cstdint>

// RNNModel: g = [E|R]@[We|Wr]^T + (be+br+bh)  (proj, relu on t==0 rows)
//           h_t = relu(g_t + h_{t-1}@Wh^T)    (7 in-place GEMM launches)
//           need = h_7^T                       (tiled transpose)
// TF32 mma.sync.m16n8k8, 128x128x32 CTA tiles, 16 warps (32x32 warp tile).
// R4: register-fragment double-buffer pipeline (LDSM ks+1 ahead of MMA ks),
//     LDG prefetch distance 2, double-buffered smem, 1 sync per K-tile.
// NOTE: tcgen05 unusable in this harness build (ptxas targets compute_103 base).

#define SKEW 36
#define BUFW (128 * SKEW)   // words per buffer per matrix

__device__ __forceinline__ unsigned f2tf(float x) {
    unsigned u;
    asm("cvt.rna.tf32.f32 %0, %1;" : "=r"(u) : "f"(x));
    return u;
}

__device__ __forceinline__ void mma_tf32(float c[4], const unsigned a[4], const unsigned b[2]) {
    asm volatile(
        "mma.sync.aligned.m16n8k8.row.col.f32.tf32.tf32.f32 "
        "{%0,%1,%2,%3}, {%4,%5,%6,%7}, {%8,%9}, {%0,%1,%2,%3};\n"
        : "+f"(c[0]), "+f"(c[1]), "+f"(c[2]), "+f"(c[3])
        : "r"(a[0]), "r"(a[1]), "r"(a[2]), "r"(a[3]),
          "r"(b[0]), "r"(b[1]));
}

__device__ __forceinline__ void ldsm_x4(unsigned& r0, unsigned& r1, unsigned& r2, unsigned& r3,
                                        unsigned addr) {
    asm volatile("ldmatrix.sync.aligned.m8n8.x4.shared.b16 {%0,%1,%2,%3}, [%4];\n"
                 : "=r"(r0), "=r"(r1), "=r"(r2), "=r"(r3)
                 : "r"(addr));
}

// MODE 0: C[65536,1024] = [E|R] @ [We|Wr]^T + (be+br+bh); relu on rows with row%8==0
// MODE 1: C rows (stride 8192) = relu(C + A @ Wh^T), A stride 8192
template<int MODE>
__global__ __launch_bounds__(512, 1)
void gemm_k(const float* A0, const float* A1,
            const float* __restrict__ B0, const float* __restrict__ B1,
            const float* __restrict__ be, const float* __restrict__ br,
            const float* __restrict__ bhp,
            float* C)
{
    constexpr int KTOT = (MODE == 0) ? 1536 : 1024;
    constexpr int LDC  = (MODE == 0) ? 1024 : 8192;
    constexpr int NKT  = KTOT / 32;

    extern __shared__ unsigned sh[];
    unsigned* sA = sh;               // [2][BUFW]
    unsigned* sB = sh + 2 * BUFW;    // [2][BUFW]
    float* sBias = (float*)(sh + 4 * BUFW);  // [128]

    const int tid = threadIdx.x;
    const int bN  = blockIdx.x;
    const int bM  = blockIdx.y;

    if (MODE == 0) {
        if (tid < 128) {
            int c = bN * 128 + tid;
            sBias[tid] = be[c] + br[c] + bhp[c];
        }
    }

    const int lane = tid & 31;
    const int warp = tid >> 5;
    const int wm = warp & 3;      // 4 M-warps of 32 rows
    const int wn = warp >> 2;     // 4 N-warps of 32 cols
    const int grp = lane >> 2;
    const int qid = lane & 3;

    // global->smem staging: 2 x 16B chunks per matrix per thread
    int lrow[2], lc4[2], soff[2];
    #pragma unroll
    for (int i = 0; i < 2; ++i) {
        int f = tid + i * 512;
        lrow[i] = f >> 3;
        lc4[i]  = (f & 7) * 4;
        soff[i] = lrow[i] * SKEW + lc4[i];
    }

    // ldmatrix per-thread addresses (bytes, shared space), buffer 0.
    const unsigned aBase = (unsigned)__cvta_generic_to_shared(sA);
    const unsigned bBase = (unsigned)__cvta_generic_to_shared(sB);
    const int rA = wm * 32 + ((lane >> 3) & 1) * 8 + (lane & 7);
    const int kA = ((lane >> 4) & 1) * 4;
    unsigned aAddr[2];
    #pragma unroll
    for (int mt = 0; mt < 2; ++mt)
        aAddr[mt] = aBase + (unsigned)(((rA + mt * 16) * SKEW + kA) * 4);
    const int rB = wn * 32 + ((lane >> 4) & 1) * 8 + (lane & 7);
    const int kB = ((lane >> 3) & 1) * 4;
    unsigned bAddr[2];
    #pragma unroll
    for (int p = 0; p < 2; ++p)
        bAddr[p] = bBase + (unsigned)(((rB + p * 16) * SKEW + kB) * 4);

    float4 ra[2], rb[2];

    auto loadA = [&](int kt) {
        #pragma unroll
        for (int i = 0; i < 2; ++i) {
            int gr = bM * 128 + lrow[i];
            int gk = kt * 32 + lc4[i];
            const float* p;
            if (MODE == 0) {
                p = (gk < 512) ? (A0 + (size_t)gr * 512 + gk)
                               : (A1 + (size_t)gr * 1024 + (gk - 512));
            } else {
                p = A0 + (size_t)gr * 8192 + gk;
            }
            ra[i] = *(const float4*)p;
        }
    };
    auto loadB = [&](int kt) {
        #pragma unroll
        for (int i = 0; i < 2; ++i) {
            int gn = bN * 128 + lrow[i];
            int gk = kt * 32 + lc4[i];
            const float* p;
            if (MODE == 0) {
                p = (gk < 512) ? (B0 + (size_t)gn * 512 + gk)
                               : (B1 + (size_t)gn * 1024 + (gk - 512));
            } else {
                p = B0 + (size_t)gn * 1024 + gk;
            }
            rb[i] = *(const float4*)p;
        }
    };
    auto stsTile = [&](int b) {
        const int bo = b * BUFW;
        #pragma unroll
        for (int i = 0; i < 2; ++i) {
            uint4 va = make_uint4(f2tf(ra[i].x), f2tf(ra[i].y), f2tf(ra[i].z), f2tf(ra[i].w));
            uint4 vb = make_uint4(f2tf(rb[i].x), f2tf(rb[i].y), f2tf(rb[i].z), f2tf(rb[i].w));
            *(uint4*)&sA[bo + soff[i]] = va;
            *(uint4*)&sB[bo + soff[i]] = vb;
        }
    };

    // register fragment double buffer
    unsigned afr0[2][4], afr1[2][4];
    unsigned bfr0[4][2], bfr1[4][2];

    auto ldF = [&](unsigned (&af)[2][4], unsigned (&bf)[4][2], unsigned base) {
        #pragma unroll
        for (int mt = 0; mt < 2; ++mt)
            ldsm_x4(af[mt][0], af[mt][1], af[mt][2], af[mt][3], aAddr[mt] + base);
        #pragma unroll
        for (int p = 0; p < 2; ++p)
            ldsm_x4(bf[2 * p][0], bf[2 * p][1], bf[2 * p + 1][0], bf[2 * p + 1][1],
                    bAddr[p] + base);
    };

    float acc[2][4][4];
    #pragma unroll
    for (int mt = 0; mt < 2; ++mt)
        #pragma unroll
        for (int nt = 0; nt < 4; ++nt)
            #pragma unroll
            for (int j = 0; j < 4; ++j) acc[mt][nt][j] = 0.f;

    auto mmaF = [&](unsigned (&af)[2][4], unsigned (&bf)[4][2]) {
        #pragma unroll
        for (int mt = 0; mt < 2; ++mt)
            #pragma unroll
            for (int nt = 0; nt < 4; ++nt)
                mma_tf32(acc[mt][nt], af[mt], bf[nt]);
    };

    // prologue: fill buffer 0, prime frag pipe, start LDG for kt=1
    loadA(0); loadB(0);
    stsTile(0);
    __syncthreads();
    if (NKT > 1) { loadA(1); loadB(1); }
    ldF(afr0, bfr0, 0u);                      // buf0, ks0

    int buf = 0;
    for (int kt = 0; kt < NKT; ++kt) {
        const unsigned boB = (unsigned)(buf * BUFW * 4);
        ldF(afr1, bfr1, boB + 32u);           // ks1
        mmaF(afr0, bfr0);                     // ks0
        ldF(afr0, bfr0, boB + 64u);           // ks2
        mmaF(afr1, bfr1);                     // ks1
        ldF(afr1, bfr1, boB + 96u);           // ks3
        if (kt + 1 < NKT) stsTile(buf ^ 1);   // kt+1 data -> alt buffer
        mmaF(afr0, bfr0);                     // ks2
        __syncthreads();
        if (kt + 2 < NKT) { loadA(kt + 2); loadB(kt + 2); }
        if (kt + 1 < NKT)
            ldF(afr0, bfr0, (unsigned)((buf ^ 1) * BUFW * 4));  // next tile ks0
        mmaF(afr1, bfr1);                     // ks3
        buf ^= 1;
    }

    // epilogue
    #pragma unroll
    for (int mt = 0; mt < 2; ++mt) {
        int r0 = bM * 128 + wm * 32 + mt * 16 + grp;
        #pragma unroll
        for (int nt = 0; nt < 4; ++nt) {
            int col  = bN * 128 + wn * 32 + nt * 8 + qid * 2;
            int colL = wn * 32 + nt * 8 + qid * 2;
            if (MODE == 0) {
                float b0 = sBias[colL];
                float b1 = sBias[colL + 1];
                float x0 = acc[mt][nt][0] + b0;
                float x1 = acc[mt][nt][1] + b1;
                float x2 = acc[mt][nt][2] + b0;
                float x3 = acc[mt][nt][3] + b1;
                if (grp == 0) {   // rows with r0 % 8 == 0 are t==0: relu (step 0 folded)
                    x0 = fmaxf(x0, 0.f); x1 = fmaxf(x1, 0.f);
                    x2 = fmaxf(x2, 0.f); x3 = fmaxf(x3, 0.f);
                }
                *(float2*)(C + (size_t)r0 * LDC + col)       = make_float2(x0, x1);
                *(float2*)(C + (size_t)(r0 + 8) * LDC + col) = make_float2(x2, x3);
            } else {
                float* p0 = C + (size_t)r0 * LDC + col;
                float* p1 = C + (size_t)(r0 + 8) * LDC + col;
                float2 g0 = *(float2*)p0;
                float2 g1 = *(float2*)p1;
                *(float2*)p0 = make_float2(fmaxf(acc[mt][nt][0] + g0.x, 0.f),
                                           fmaxf(acc[mt][nt][1] + g0.y, 0.f));
                *(float2*)p1 = make_float2(fmaxf(acc[mt][nt][2] + g1.x, 0.f),
                                           fmaxf(acc[mt][nt][3] + g1.y, 0.f));
            }
        }
    }
}

// need[h, b] = out[b, 7, h]   (out row stride 8192, t=7 offset 7168)
__global__ void transpose_k(const float* __restrict__ out, float* __restrict__ need)
{
    __shared__ float tile[32][33];
    int h0 = blockIdx.x * 32;
    int b0 = blockIdx.y * 32;
    int x = threadIdx.x;
    int y = threadIdx.y;
    #pragma unroll
    for (int j = 0; j < 32; j += 8)
        tile[y + j][x] = out[(size_t)(b0 + y + j) * 8192 + 7168 + h0 + x];
    __syncthreads();
    #pragma unroll
    for (int j = 0; j < 32; j += 8)
        need[(size_t)(h0 + y + j) * 8192 + b0 + x] = tile[x][y + j];
}

extern "C" void kernel_launch(void* const* d_in, const int* in_sizes, int n_in,
                              void* d_out, int out_size)
{
    const float* entity   = (const float*)d_in[0];  // [8192, 8, 512]
    const float* relation = (const float*)d_in[1];  // [8192, 8, 1024]
    const float* We       = (const float*)d_in[2];  // [1024, 512]
    const float* be       = (const float*)d_in[3];  // [1024]
    const float* Wr       = (const float*)d_in[4];  // [1024, 1024]
    const float* br       = (const float*)d_in[5];  // [1024]
    const float* Wh       = (const float*)d_in[6];  // [1024, 1024]
    const float* bh       = (const float*)d_in[7];  // [1024]

    float* out  = (float*)d_out;               // [65536, 1024]
    float* need = out + (size_t)65536 * 1024;  // [1024, 8192]

    const int smemBytes = (4 * BUFW + 128) * 4;  // 74240
    cudaFuncSetAttribute(gemm_k<0>, cudaFuncAttributeMaxDynamicSharedMemorySize, smemBytes);
    cudaFuncSetAttribute(gemm_k<1>, cudaFuncAttributeMaxDynamicSharedMemorySize, smemBytes);

    // Projection: g (all biases folded, relu applied for t==0 rows)
    gemm_k<0><<<dim3(8, 512), 512, smemBytes>>>(entity, relation, We, Wr, be, br, bh, out);

    // Recurrence: t = 1..7, in place over the g slices
    for (int t = 1; t < 8; ++t) {
        const float* Aprev = out + (size_t)(t - 1) * 1024;
        float*       Ct    = out + (size_t)t * 1024;
        gemm_k<1><<<dim3(8, 64), 512, smemBytes>>>(Aprev, nullptr, Wh, nullptr,
                                                   nullptr, nullptr, nullptr, Ct);
    }

    // need = h_7^T
    transpose_k<<<dim3(32, 256), dim3(32, 8)>>>(out, need);
}

// round 6
// speedup vs baseline: 1.1348x; 1.1348x over previous
#include <cuda_runtime.h>
#include <cuda_fp16.h>
#include <cstdint>

// RNNModel: g = [E|R]@[We|Wr]^T + (be+br+bh)  (proj, relu on t==0 rows)
//           h_t = relu(g_t + h_{t-1}@Wh^T)    (7 in-place GEMM launches)
//           need = h_7^T                       (tiled transpose)
// R5: FP16 mma.sync.m16n8k16 (fp32 accum). fp16 mantissa == tf32 mantissa (10b),
//     data is O(1) -> same accuracy as tf32, half the HMMA instructions and half
//     the LDSM/STS bytes. 128x128x32 CTA tiles, 8 warps (32x64 warp tile),
//     80B smem row stride (conflict-free ldmatrix), double-buffered smem.
// NOTE: tcgen05 unusable in this harness build (ptxas targets compute_103 base).

#define SROWH 40                 // halfs per smem row (80B)
#define BUFH  (128 * SROWH)      // halfs per buffer per matrix (5120)

__device__ __forceinline__ unsigned f2h2(float a, float b) {
    __half2 h = __float22half2_rn(make_float2(a, b));
    return *(unsigned*)&h;
}

__device__ __forceinline__ void mma_f16(float c[4], const unsigned a[4], const unsigned b[2]) {
    asm volatile(
        "mma.sync.aligned.m16n8k16.row.col.f32.f16.f16.f32 "
        "{%0,%1,%2,%3}, {%4,%5,%6,%7}, {%8,%9}, {%0,%1,%2,%3};\n"
        : "+f"(c[0]), "+f"(c[1]), "+f"(c[2]), "+f"(c[3])
        : "r"(a[0]), "r"(a[1]), "r"(a[2]), "r"(a[3]),
          "r"(b[0]), "r"(b[1]));
}

__device__ __forceinline__ void ldsm_x4(unsigned& r0, unsigned& r1, unsigned& r2, unsigned& r3,
                                        unsigned addr) {
    asm volatile("ldmatrix.sync.aligned.m8n8.x4.shared.b16 {%0,%1,%2,%3}, [%4];\n"
                 : "=r"(r0), "=r"(r1), "=r"(r2), "=r"(r3)
                 : "r"(addr));
}

// MODE 0: C[65536,1024] = [E|R] @ [We|Wr]^T + (be+br+bh); relu on rows with row%8==0
// MODE 1: C rows (stride 8192) = relu(C + A @ Wh^T), A stride 8192
template<int MODE>
__global__ __launch_bounds__(256, 1)
void gemm_k(const float* A0, const float* A1,
            const float* __restrict__ B0, const float* __restrict__ B1,
            const float* __restrict__ be, const float* __restrict__ br,
            const float* __restrict__ bhp,
            float* C)
{
    constexpr int KTOT = (MODE == 0) ? 1536 : 1024;
    constexpr int LDC  = (MODE == 0) ? 1024 : 8192;
    constexpr int NKT  = KTOT / 32;

    __shared__ __align__(16) __half sA[2 * BUFH];
    __shared__ __align__(16) __half sB[2 * BUFH];
    __shared__ float sBias[128];

    const int tid = threadIdx.x;
    const int bN  = blockIdx.x;
    const int bM  = blockIdx.y;

    if (MODE == 0) {
        if (tid < 128) {
            int c = bN * 128 + tid;
            sBias[tid] = be[c] + br[c] + bhp[c];
        }
    }

    const int lane = tid & 31;
    const int warp = tid >> 5;
    const int wm = warp & 3;      // 4 M-warps of 32 rows
    const int wn = warp >> 2;     // 2 N-warps of 64 cols
    const int grp = lane >> 2;
    const int qid = lane & 3;

    // staging: 2 chunks (16B = 8 fp16 = 8 fp32 gmem) per matrix per thread
    int srow[2], sch[2];
    #pragma unroll
    for (int i = 0; i < 2; ++i) {
        int slot = tid + i * 256;
        srow[i] = slot >> 2;      // 0..127
        sch[i]  = slot & 3;       // 16B chunk in row
    }

    // ldmatrix base addresses (bytes, buffer 0)
    const unsigned aBase = (unsigned)__cvta_generic_to_shared(sA);
    const unsigned bBase = (unsigned)__cvta_generic_to_shared(sB);
    // A m16k16 frag: tiles (m,k0)(m+8,k0)(m,k8)(m+8,k8)
    const int rA = wm * 32 + (lane & 7) + ((lane >> 3) & 1) * 8;
    const int kselA = (lane >> 4) & 1;
    unsigned aAddr[2];
    #pragma unroll
    for (int mt = 0; mt < 2; ++mt)
        aAddr[mt] = aBase + (unsigned)((rA + mt * 16) * 80 + kselA * 16);
    // B pair frag: tiles (n,k0)(n,k8)(n+8,k0)(n+8,k8)
    const int rB = wn * 64 + (lane & 7) + ((lane >> 4) & 1) * 8;
    const int kselB = (lane >> 3) & 1;
    unsigned bAddr[4];
    #pragma unroll
    for (int p = 0; p < 4; ++p)
        bAddr[p] = bBase + (unsigned)((rB + p * 16) * 80 + kselB * 16);

    float4 ra[2][2], rb[2][2];

    auto loadA = [&](int kt) {
        #pragma unroll
        for (int i = 0; i < 2; ++i) {
            int gr = bM * 128 + srow[i];
            int gk = kt * 32 + sch[i] * 8;
            const float* p;
            if (MODE == 0) {
                p = (gk < 512) ? (A0 + (size_t)gr * 512 + gk)
                               : (A1 + (size_t)gr * 1024 + (gk - 512));
            } else {
                p = A0 + (size_t)gr * 8192 + gk;
            }
            ra[i][0] = *(const float4*)p;
            ra[i][1] = *(const float4*)(p + 4);
        }
    };
    auto loadB = [&](int kt) {
        #pragma unroll
        for (int i = 0; i < 2; ++i) {
            int gn = bN * 128 + srow[i];
            int gk = kt * 32 + sch[i] * 8;
            const float* p;
            if (MODE == 0) {
                p = (gk < 512) ? (B0 + (size_t)gn * 512 + gk)
                               : (B1 + (size_t)gn * 1024 + (gk - 512));
            } else {
                p = B0 + (size_t)gn * 1024 + gk;
            }
            rb[i][0] = *(const float4*)p;
            rb[i][1] = *(const float4*)(p + 4);
        }
    };
    auto stsTile = [&](int b) {
        #pragma unroll
        for (int i = 0; i < 2; ++i) {
            int off = b * BUFH + srow[i] * SROWH + sch[i] * 8;   // halfs
            uint4 va = make_uint4(f2h2(ra[i][0].x, ra[i][0].y), f2h2(ra[i][0].z, ra[i][0].w),
                                  f2h2(ra[i][1].x, ra[i][1].y), f2h2(ra[i][1].z, ra[i][1].w));
            uint4 vb = make_uint4(f2h2(rb[i][0].x, rb[i][0].y), f2h2(rb[i][0].z, rb[i][0].w),
                                  f2h2(rb[i][1].x, rb[i][1].y), f2h2(rb[i][1].z, rb[i][1].w));
            *(uint4*)&sA[off] = va;
            *(uint4*)&sB[off] = vb;
        }
    };

    float acc[2][8][4];
    #pragma unroll
    for (int mt = 0; mt < 2; ++mt)
        #pragma unroll
        for (int nt = 0; nt < 8; ++nt)
            #pragma unroll
            for (int j = 0; j < 4; ++j) acc[mt][nt][j] = 0.f;

    loadA(0); loadB(0);

    int buf = 0;
    for (int kt = 0; kt < NKT; ++kt) {
        stsTile(buf);
        __syncthreads();
        if (kt + 1 < NKT) { loadA(kt + 1); loadB(kt + 1); }

        const unsigned boB = (unsigned)(buf * BUFH * 2);   // bytes
        #pragma unroll
        for (int ks = 0; ks < 2; ++ks) {
            const unsigned ko = boB + ks * 32u;            // ks1 -> +32B (k16..31)
            unsigned afr[2][4];
            #pragma unroll
            for (int mt = 0; mt < 2; ++mt)
                ldsm_x4(afr[mt][0], afr[mt][1], afr[mt][2], afr[mt][3], aAddr[mt] + ko);
            unsigned bfr[8][2];
            #pragma unroll
            for (int p = 0; p < 4; ++p)
                ldsm_x4(bfr[2 * p][0], bfr[2 * p][1], bfr[2 * p + 1][0], bfr[2 * p + 1][1],
                        bAddr[p] + ko);
            #pragma unroll
            for (int mt = 0; mt < 2; ++mt)
                #pragma unroll
                for (int nt = 0; nt < 8; ++nt)
                    mma_f16(acc[mt][nt], afr[mt], bfr[nt]);
        }
        __syncthreads();
        buf ^= 1;
    }

    // epilogue (C fragment layout identical to tf32 path)
    #pragma unroll
    for (int mt = 0; mt < 2; ++mt) {
        int r0 = bM * 128 + wm * 32 + mt * 16 + grp;
        #pragma unroll
        for (int nt = 0; nt < 8; ++nt) {
            int col  = bN * 128 + wn * 64 + nt * 8 + qid * 2;
            int colL = wn * 64 + nt * 8 + qid * 2;
            if (MODE == 0) {
                float b0 = sBias[colL];
                float b1 = sBias[colL + 1];
                float x0 = acc[mt][nt][0] + b0;
                float x1 = acc[mt][nt][1] + b1;
                float x2 = acc[mt][nt][2] + b0;
                float x3 = acc[mt][nt][3] + b1;
                if (grp == 0) {   // rows with r0 % 8 == 0 are t==0: relu (step 0 folded)
                    x0 = fmaxf(x0, 0.f); x1 = fmaxf(x1, 0.f);
                    x2 = fmaxf(x2, 0.f); x3 = fmaxf(x3, 0.f);
                }
                *(float2*)(C + (size_t)r0 * LDC + col)       = make_float2(x0, x1);
                *(float2*)(C + (size_t)(r0 + 8) * LDC + col) = make_float2(x2, x3);
            } else {
                float* p0 = C + (size_t)r0 * LDC + col;
                float* p1 = C + (size_t)(r0 + 8) * LDC + col;
                float2 g0 = *(float2*)p0;
                float2 g1 = *(float2*)p1;
                *(float2*)p0 = make_float2(fmaxf(acc[mt][nt][0] + g0.x, 0.f),
                                           fmaxf(acc[mt][nt][1] + g0.y, 0.f));
                *(float2*)p1 = make_float2(fmaxf(acc[mt][nt][2] + g1.x, 0.f),
                                           fmaxf(acc[mt][nt][3] + g1.y, 0.f));
            }
        }
    }
}

// need[h, b] = out[b, 7, h]   (out row stride 8192, t=7 offset 7168)
__global__ void transpose_k(const float* __restrict__ out, float* __restrict__ need)
{
    __shared__ float tile[32][33];
    int h0 = blockIdx.x * 32;
    int b0 = blockIdx.y * 32;
    int x = threadIdx.x;
    int y = threadIdx.y;
    #pragma unroll
    for (int j = 0; j < 32; j += 8)
        tile[y + j][x] = out[(size_t)(b0 + y + j) * 8192 + 7168 + h0 + x];
    __syncthreads();
    #pragma unroll
    for (int j = 0; j < 32; j += 8)
        need[(size_t)(h0 + y + j) * 8192 + b0 + x] = tile[x][y + j];
}

extern "C" void kernel_launch(void* const* d_in, const int* in_sizes, int n_in,
                              void* d_out, int out_size)
{
    const float* entity   = (const float*)d_in[0];  // [8192, 8, 512]
    const float* relation = (const float*)d_in[1];  // [8192, 8, 1024]
    const float* We       = (const float*)d_in[2];  // [1024, 512]
    const float* be       = (const float*)d_in[3];  // [1024]
    const float* Wr       = (const float*)d_in[4];  // [1024, 1024]
    const float* br       = (const float*)d_in[5];  // [1024]
    const float* Wh       = (const float*)d_in[6];  // [1024, 1024]
    const float* bh       = (const float*)d_in[7];  // [1024]

    float* out  = (float*)d_out;               // [65536, 1024]
    float* need = out + (size_t)65536 * 1024;  // [1024, 8192]

    // Projection: g (all biases folded, relu applied for t==0 rows)
    gemm_k<0><<<dim3(8, 512), 256>>>(entity, relation, We, Wr, be, br, bh, out);

    // Recurrence: t = 1..7, in place over the g slices
    for (int t = 1; t < 8; ++t) {
        const float* Aprev = out + (size_t)(t - 1) * 1024;
        float*       Ct    = out + (size_t)t * 1024;
        gemm_k<1><<<dim3(8, 64), 256>>>(Aprev, nullptr, Wh, nullptr,
                                        nullptr, nullptr, nullptr, Ct);
    }

    // need = h_7^T
    transpose_k<<<dim3(32, 256), dim3(32, 8)>>>(out, need);
}

// round 7
// speedup vs baseline: 1.7007x; 1.4986x over previous
#include <cuda_runtime.h>
#include <cuda_fp16.h>
#include <cstdint>

// RNNModel: g = [E|R]@[We|Wr]^T + (be+br+bh)  (proj, relu on t==0 rows)
//           h_t = relu(g_t + h_{t-1}@Wh^T)    (7 in-place GEMM launches)
//           need = h_7^T
// R6: fp16 operands pre-converted in gmem (prepass + epilogue fp16 h writes),
//     cp.async.cg 4-stage pipeline, K-stage 64, 144B smem rows (conflict-free
//     ldmatrix), mma.sync.m16n8k16.f16 with fp32 accum.
// NOTE: tcgen05 unusable in this harness build (ptxas targets compute_103 base).

#define STAGES   4
#define SROWB    144                 // bytes per smem row (64 halfs + pad)
#define STAGE_B  18432               // 128 * 144
#define B_REGION (STAGES * STAGE_B)  // 73728
#define SMEM_SZ  (2 * B_REGION + 512)

// fp16 scratch (device-global: allocation-free)
__device__ __half g_A16[(size_t)65536 * 1536];   // packed [E|R]
__device__ __half g_W16[1024 * 1536];            // packed [We|Wr]
__device__ __half g_Wh16[1024 * 1024];
__device__ __half g_H16[(size_t)65536 * 1024];   // h_t fp16, same row indexing as out

__device__ __forceinline__ void mma_f16(float c[4], const unsigned a[4], const unsigned b[2]) {
    asm volatile(
        "mma.sync.aligned.m16n8k16.row.col.f32.f16.f16.f32 "
        "{%0,%1,%2,%3}, {%4,%5,%6,%7}, {%8,%9}, {%0,%1,%2,%3};\n"
        : "+f"(c[0]), "+f"(c[1]), "+f"(c[2]), "+f"(c[3])
        : "r"(a[0]), "r"(a[1]), "r"(a[2]), "r"(a[3]),
          "r"(b[0]), "r"(b[1]));
}
__device__ __forceinline__ void ldsm_x4(unsigned& r0, unsigned& r1, unsigned& r2, unsigned& r3,
                                        unsigned addr) {
    asm volatile("ldmatrix.sync.aligned.m8n8.x4.shared.b16 {%0,%1,%2,%3}, [%4];\n"
                 : "=r"(r0), "=r"(r1), "=r"(r2), "=r"(r3)
                 : "r"(addr));
}
__device__ __forceinline__ void cp16(unsigned dst, const void* src) {
    asm volatile("cp.async.cg.shared.global [%0], [%1], 16;" :: "r"(dst), "l"(src));
}
__device__ __forceinline__ void cp_commit() {
    asm volatile("cp.async.commit_group;" ::: "memory");
}
__device__ __forceinline__ void cp_wait2() {
    asm volatile("cp.async.wait_group 2;" ::: "memory");
}

// MODE 0: C[65536,1024] = A16 @ W16^T + bias; relu + H16 write on rows%8==0.
// MODE 1: C(+t*1024 by host) = relu(C + H16(t-1) @ Wh16^T); writes H16(t).
template<int MODE>
__global__ __launch_bounds__(256, 1)
void gemm16(int t, const float* __restrict__ be, const float* __restrict__ br,
            const float* __restrict__ bhp, float* C)
{
    constexpr int KTOT = MODE ? 1024 : 1536;
    constexpr int NKT  = KTOT / 64;
    constexpr int LDA  = MODE ? 8192 : 1536;
    constexpr int LDB  = MODE ? 1024 : 1536;
    constexpr int LDC  = MODE ? 8192 : 1024;

    extern __shared__ __align__(16) char sm[];
    float* sBias = (float*)(sm + 2 * B_REGION);
    const unsigned smBase = (unsigned)__cvta_generic_to_shared(sm);

    const int tid = threadIdx.x;
    const int bN  = blockIdx.x;
    const int bM  = blockIdx.y;

    const __half* A = MODE ? g_H16 + (size_t)(t - 1) * 1024 : g_A16;
    const __half* B = MODE ? g_Wh16 : g_W16;
    __half* Hout = MODE ? g_H16 + (size_t)t * 1024 : g_H16;
    const int ldH = MODE ? 8192 : 1024;

    if (MODE == 0) {
        if (tid < 128) {
            int c = bN * 128 + tid;
            sBias[tid] = be[c] + br[c] + bhp[c];
        }
    }

    const int lane = tid & 31;
    const int warp = tid >> 5;
    const int wm = warp & 3;      // 4 M-warps of 32 rows
    const int wn = warp >> 2;     // 2 N-warps of 64 cols
    const int grp = lane >> 4;    // placeholder (recomputed below)
    const int g8  = lane >> 2;
    const int qid = lane & 3;
    (void)grp;

    // cp.async chunk mapping: 4 chunks/matrix/thread, chunk c -> row=c>>3, ch=c&7
    int crow[4], cch[4];
    #pragma unroll
    for (int i = 0; i < 4; ++i) {
        int c = tid + i * 256;
        crow[i] = c >> 3;
        cch[i]  = c & 7;
    }

    auto stageLoad = [&](int kt) {
        const int st = kt & (STAGES - 1);
        const unsigned dA = smBase + st * STAGE_B;
        const unsigned dB = smBase + B_REGION + st * STAGE_B;
        #pragma unroll
        for (int i = 0; i < 4; ++i) {
            const int gk = kt * 64 + cch[i] * 8;
            cp16(dA + crow[i] * SROWB + cch[i] * 16,
                 A + (size_t)(bM * 128 + crow[i]) * LDA + gk);
            cp16(dB + crow[i] * SROWB + cch[i] * 16,
                 B + (size_t)(bN * 128 + crow[i]) * LDB + gk);
        }
        cp_commit();
    };

    // ldmatrix base addresses (stage 0)
    const int rA = wm * 32 + (lane & 7) + ((lane >> 3) & 1) * 8;
    const int kselA = (lane >> 4) & 1;
    unsigned aAddr[2];
    #pragma unroll
    for (int mt = 0; mt < 2; ++mt)
        aAddr[mt] = smBase + (unsigned)((rA + mt * 16) * SROWB + kselA * 16);
    const int rB = wn * 64 + (lane & 7) + ((lane >> 4) & 1) * 8;
    const int kselB = (lane >> 3) & 1;
    unsigned bAddr[4];
    #pragma unroll
    for (int p = 0; p < 4; ++p)
        bAddr[p] = smBase + (unsigned)(B_REGION + (rB + p * 16) * SROWB + kselB * 16);

    float acc[2][8][4];
    #pragma unroll
    for (int mt = 0; mt < 2; ++mt)
        #pragma unroll
        for (int nt = 0; nt < 8; ++nt)
            #pragma unroll
            for (int j = 0; j < 4; ++j) acc[mt][nt][j] = 0.f;

    // prologue: 3 stages in flight
    stageLoad(0); stageLoad(1); stageLoad(2);

    for (int kt = 0; kt < NKT; ++kt) {
        cp_wait2();
        __syncthreads();
        const unsigned so = (unsigned)((kt & (STAGES - 1)) * STAGE_B);
        #pragma unroll
        for (int ks = 0; ks < 4; ++ks) {
            const unsigned ko = so + ks * 32u;
            unsigned afr[2][4];
            #pragma unroll
            for (int mt = 0; mt < 2; ++mt)
                ldsm_x4(afr[mt][0], afr[mt][1], afr[mt][2], afr[mt][3], aAddr[mt] + ko);
            unsigned bfr[8][2];
            #pragma unroll
            for (int p = 0; p < 4; ++p)
                ldsm_x4(bfr[2 * p][0], bfr[2 * p][1], bfr[2 * p + 1][0], bfr[2 * p + 1][1],
                        bAddr[p] + ko);
            #pragma unroll
            for (int mt = 0; mt < 2; ++mt)
                #pragma unroll
                for (int nt = 0; nt < 8; ++nt)
                    mma_f16(acc[mt][nt], afr[mt], bfr[nt]);
        }
        __syncthreads();
        if (kt + STAGES - 1 < NKT) stageLoad(kt + STAGES - 1);
        else cp_commit();   // keep group accounting valid for wait_group 2
    }

    // epilogue
    #pragma unroll
    for (int mt = 0; mt < 2; ++mt) {
        int r0 = bM * 128 + wm * 32 + mt * 16 + g8;
        #pragma unroll
        for (int nt = 0; nt < 8; ++nt) {
            int col  = bN * 128 + wn * 64 + nt * 8 + qid * 2;
            int colL = wn * 64 + nt * 8 + qid * 2;
            if (MODE == 0) {
                float b0 = sBias[colL];
                float b1 = sBias[colL + 1];
                float x0 = acc[mt][nt][0] + b0;
                float x1 = acc[mt][nt][1] + b1;
                float x2 = acc[mt][nt][2] + b0;
                float x3 = acc[mt][nt][3] + b1;
                if (g8 == 0) {   // rows%8==0 are t==0: relu + fp16 h0
                    x0 = fmaxf(x0, 0.f); x1 = fmaxf(x1, 0.f);
                    x2 = fmaxf(x2, 0.f); x3 = fmaxf(x3, 0.f);
                    *(__half2*)(Hout + (size_t)r0 * ldH + col)       = __floats2half2_rn(x0, x1);
                    *(__half2*)(Hout + (size_t)(r0 + 8) * ldH + col) = __floats2half2_rn(x2, x3);
                }
                *(float2*)(C + (size_t)r0 * LDC + col)       = make_float2(x0, x1);
                *(float2*)(C + (size_t)(r0 + 8) * LDC + col) = make_float2(x2, x3);
            } else {
                float* p0 = C + (size_t)r0 * LDC + col;
                float* p1 = C + (size_t)(r0 + 8) * LDC + col;
                float2 g0 = *(float2*)p0;
                float2 g1 = *(float2*)p1;
                float x0 = fmaxf(acc[mt][nt][0] + g0.x, 0.f);
                float x1 = fmaxf(acc[mt][nt][1] + g0.y, 0.f);
                float x2 = fmaxf(acc[mt][nt][2] + g1.x, 0.f);
                float x3 = fmaxf(acc[mt][nt][3] + g1.y, 0.f);
                *(float2*)p0 = make_float2(x0, x1);
                *(float2*)p1 = make_float2(x2, x3);
                *(__half2*)(Hout + (size_t)r0 * ldH + col)       = __floats2half2_rn(x0, x1);
                *(__half2*)(Hout + (size_t)(r0 + 8) * ldH + col) = __floats2half2_rn(x2, x3);
            }
        }
    }
}

// pack two fp32 sources (widths 512 and 1024) into one fp16 row of 1536
template<int DST>  // 0 -> g_A16, 1 -> g_W16
__global__ void pack16(const float* __restrict__ s0, const float* __restrict__ s1, int rows)
{
    __half* dst = DST ? g_W16 : g_A16;
    size_t cid = (size_t)blockIdx.x * 256 + threadIdx.x;   // 8 cols each
    if (cid >= (size_t)rows * 192) return;
    int row = (int)(cid / 192);
    int c8  = (int)(cid % 192) * 8;
    const float* p = (c8 < 512) ? (s0 + (size_t)row * 512 + c8)
                                : (s1 + (size_t)row * 1024 + (c8 - 512));
    float4 v0 = ((const float4*)p)[0];
    float4 v1 = ((const float4*)p)[1];
    __half2 h0 = __floats2half2_rn(v0.x, v0.y);
    __half2 h1 = __floats2half2_rn(v0.z, v0.w);
    __half2 h2 = __floats2half2_rn(v1.x, v1.y);
    __half2 h3 = __floats2half2_rn(v1.z, v1.w);
    uint4 o = make_uint4(*(unsigned*)&h0, *(unsigned*)&h1, *(unsigned*)&h2, *(unsigned*)&h3);
    *(uint4*)(dst + (size_t)row * 1536 + c8) = o;
}

__global__ void cvt16(const float* __restrict__ src, int n)   // -> g_Wh16
{
    size_t i = ((size_t)blockIdx.x * 256 + threadIdx.x) * 8;
    if (i >= (size_t)n) return;
    float4 v0 = ((const float4*)(src + i))[0];
    float4 v1 = ((const float4*)(src + i))[1];
    __half2 h0 = __floats2half2_rn(v0.x, v0.y);
    __half2 h1 = __floats2half2_rn(v0.z, v0.w);
    __half2 h2 = __floats2half2_rn(v1.x, v1.y);
    __half2 h3 = __floats2half2_rn(v1.z, v1.w);
    *(uint4*)(g_Wh16 + i) = make_uint4(*(unsigned*)&h0, *(unsigned*)&h1,
                                       *(unsigned*)&h2, *(unsigned*)&h3);
}

// need[h, b] = out[b, 7, h]
__global__ void transpose_k(const float* __restrict__ out, float* __restrict__ need)
{
    __shared__ float tile[32][33];
    int h0 = blockIdx.x * 32;
    int b0 = blockIdx.y * 32;
    int x = threadIdx.x;
    int y = threadIdx.y;
    #pragma unroll
    for (int j = 0; j < 32; j += 8)
        tile[y + j][x] = out[(size_t)(b0 + y + j) * 8192 + 7168 + h0 + x];
    __syncthreads();
    #pragma unroll
    for (int j = 0; j < 32; j += 8)
        need[(size_t)(h0 + y + j) * 8192 + b0 + x] = tile[x][y + j];
}

extern "C" void kernel_launch(void* const* d_in, const int* in_sizes, int n_in,
                              void* d_out, int out_size)
{
    const float* entity   = (const float*)d_in[0];
    const float* relation = (const float*)d_in[1];
    const float* We       = (const float*)d_in[2];
    const float* be       = (const float*)d_in[3];
    const float* Wr       = (const float*)d_in[4];
    const float* br       = (const float*)d_in[5];
    const float* Wh       = (const float*)d_in[6];
    const float* bh       = (const float*)d_in[7];

    float* out  = (float*)d_out;               // [65536, 1024]
    float* need = out + (size_t)65536 * 1024;  // [1024, 8192]

    cudaFuncSetAttribute(gemm16<0>, cudaFuncAttributeMaxDynamicSharedMemorySize, SMEM_SZ);
    cudaFuncSetAttribute(gemm16<1>, cudaFuncAttributeMaxDynamicSharedMemorySize, SMEM_SZ);

    // prepass: fp16 conversions
    pack16<0><<<(int)(((size_t)65536 * 192 + 255) / 256), 256>>>(entity, relation, 65536);
    pack16<1><<<(1024 * 192 + 255) / 256, 256>>>(We, Wr, 1024);
    cvt16<<<(1024 * 1024 / 8 + 255) / 256, 256>>>(Wh, 1024 * 1024);

    // projection
    gemm16<0><<<dim3(8, 512), 256, SMEM_SZ>>>(0, be, br, bh, out);

    // recurrence
    for (int t = 1; t < 8; ++t)
        gemm16<1><<<dim3(8, 64), 256, SMEM_SZ>>>(t, nullptr, nullptr, nullptr,
                                                 out + (size_t)t * 1024);

    transpose_k<<<dim3(32, 256), dim3(32, 8)>>>(out, need);
}

// round 8
// speedup vs baseline: 1.9228x; 1.1306x over previous
#include <cuda_runtime.h>
#include <cuda_fp16.h>
#include <cstdint>

// RNNModel: g = [E|R]@[We|Wr]^T + (be+br+bh)  (proj, relu on t==0 rows)
//           h_t = relu(g_t + h_{t-1}@Wh^T)    (7 in-place GEMM launches)
//           need = h_7^T
// R7: CTA tile 256x128, warp tile 64x64 (32 MMA per 8 LDSM), fp16 operands
//     pre-converted in gmem, 3-stage cp.async.cg pipeline, K-stage 64,
//     144B smem rows, mma.sync.m16n8k16.f16 fp32-accum.
// NOTE: tcgen05 unusable in this harness build (ptxas targets compute_103 base).

#define STAGES    3
#define SROWB     144                   // bytes per smem row (64 halfs + pad)
#define A_STAGE_B (256 * SROWB)         // 36864
#define B_STAGE_B (128 * SROWB)         // 18432
#define A_REGION  (STAGES * A_STAGE_B)  // 110592
#define SMEM_SZ   (A_REGION + STAGES * B_STAGE_B + 512)   // 166400

// fp16 scratch (device-global: allocation-free)
__device__ __half g_A16[(size_t)65536 * 1536];   // packed [E|R]
__device__ __half g_W16[1024 * 1536];            // packed [We|Wr]
__device__ __half g_Wh16[1024 * 1024];
__device__ __half g_H16[(size_t)65536 * 1024];   // h_t fp16, same row indexing as out

__device__ __forceinline__ void mma_f16(float c[4], const unsigned a[4], const unsigned b[2]) {
    asm volatile(
        "mma.sync.aligned.m16n8k16.row.col.f32.f16.f16.f32 "
        "{%0,%1,%2,%3}, {%4,%5,%6,%7}, {%8,%9}, {%0,%1,%2,%3};\n"
        : "+f"(c[0]), "+f"(c[1]), "+f"(c[2]), "+f"(c[3])
        : "r"(a[0]), "r"(a[1]), "r"(a[2]), "r"(a[3]),
          "r"(b[0]), "r"(b[1]));
}
__device__ __forceinline__ void ldsm_x4(unsigned& r0, unsigned& r1, unsigned& r2, unsigned& r3,
                                        unsigned addr) {
    asm volatile("ldmatrix.sync.aligned.m8n8.x4.shared.b16 {%0,%1,%2,%3}, [%4];\n"
                 : "=r"(r0), "=r"(r1), "=r"(r2), "=r"(r3)
                 : "r"(addr));
}
__device__ __forceinline__ void cp16(unsigned dst, const void* src) {
    asm volatile("cp.async.cg.shared.global [%0], [%1], 16;" :: "r"(dst), "l"(src));
}
__device__ __forceinline__ void cp_commit() {
    asm volatile("cp.async.commit_group;" ::: "memory");
}
__device__ __forceinline__ void cp_wait1() {
    asm volatile("cp.async.wait_group 1;" ::: "memory");
}

// MODE 0: C[65536,1024] = A16 @ W16^T + bias; relu + H16 write on rows%8==0.
// MODE 1: C(+t*1024 by host) = relu(C + H16(t-1) @ Wh16^T); writes H16(t).
template<int MODE>
__global__ __launch_bounds__(256, 1)
void gemm16(int t, const float* __restrict__ be, const float* __restrict__ br,
            const float* __restrict__ bhp, float* C)
{
    constexpr int KTOT = MODE ? 1024 : 1536;
    constexpr int NKT  = KTOT / 64;
    constexpr int LDA  = MODE ? 8192 : 1536;
    constexpr int LDB  = MODE ? 1024 : 1536;
    constexpr int LDC  = MODE ? 8192 : 1024;

    extern __shared__ __align__(16) char sm[];
    float* sBias = (float*)(sm + A_REGION + STAGES * B_STAGE_B);
    const unsigned smBase = (unsigned)__cvta_generic_to_shared(sm);

    const int tid = threadIdx.x;
    const int bN  = blockIdx.x;
    const int bM  = blockIdx.y;

    const __half* A = MODE ? g_H16 + (size_t)(t - 1) * 1024 : g_A16;
    const __half* B = MODE ? g_Wh16 : g_W16;
    __half* Hout = MODE ? g_H16 + (size_t)t * 1024 : g_H16;
    const int ldH = MODE ? 8192 : 1024;

    if (MODE == 0) {
        if (tid < 128) {
            int c = bN * 128 + tid;
            sBias[tid] = be[c] + br[c] + bhp[c];
        }
    }

    const int lane = tid & 31;
    const int warp = tid >> 5;
    const int wm = warp & 3;      // 4 M-warps of 64 rows
    const int wn = warp >> 2;     // 2 N-warps of 64 cols
    const int g8  = lane >> 2;    // 0..7
    const int qid = lane & 3;

    auto stageLoad = [&](int kt) {
        const int st = kt % STAGES;
        const unsigned dA = smBase + st * A_STAGE_B;
        const unsigned dB = smBase + A_REGION + st * B_STAGE_B;
        const int gk0 = kt * 64;
        // A: 2048 16B-chunks (256 rows x 8), 8 per thread
        #pragma unroll
        for (int i = 0; i < 8; ++i) {
            int c = tid + i * 256;
            int row = c >> 3, ch = c & 7;
            cp16(dA + row * SROWB + ch * 16,
                 A + (size_t)(bM * 256 + row) * LDA + gk0 + ch * 8);
        }
        // B: 1024 chunks (128 rows x 8), 4 per thread
        #pragma unroll
        for (int i = 0; i < 4; ++i) {
            int c = tid + i * 256;
            int row = c >> 3, ch = c & 7;
            cp16(dB + row * SROWB + ch * 16,
                 B + (size_t)(bN * 128 + row) * LDB + gk0 + ch * 8);
        }
        cp_commit();
    };

    // ldmatrix base addresses (stage 0)
    const int rA = wm * 64 + (lane & 7) + ((lane >> 3) & 1) * 8;
    const int kselA = (lane >> 4) & 1;
    unsigned aAddr[4];
    #pragma unroll
    for (int mt = 0; mt < 4; ++mt)
        aAddr[mt] = smBase + (unsigned)((rA + mt * 16) * SROWB + kselA * 16);
    const int rB = wn * 64 + (lane & 7) + ((lane >> 4) & 1) * 8;
    const int kselB = (lane >> 3) & 1;
    unsigned bAddr[4];
    #pragma unroll
    for (int p = 0; p < 4; ++p)
        bAddr[p] = smBase + (unsigned)(A_REGION + (rB + p * 16) * SROWB + kselB * 16);

    float acc[4][8][4];
    #pragma unroll
    for (int mt = 0; mt < 4; ++mt)
        #pragma unroll
        for (int nt = 0; nt < 8; ++nt)
            #pragma unroll
            for (int j = 0; j < 4; ++j) acc[mt][nt][j] = 0.f;

    stageLoad(0); stageLoad(1);

    for (int kt = 0; kt < NKT; ++kt) {
        cp_wait1();
        __syncthreads();
        const unsigned soA = (unsigned)((kt % STAGES) * A_STAGE_B);
        const unsigned soB = (unsigned)((kt % STAGES) * B_STAGE_B);
        #pragma unroll
        for (int ks = 0; ks < 4; ++ks) {
            unsigned afr[4][4];
            #pragma unroll
            for (int mt = 0; mt < 4; ++mt)
                ldsm_x4(afr[mt][0], afr[mt][1], afr[mt][2], afr[mt][3],
                        aAddr[mt] + soA + ks * 32u);
            unsigned bfr[8][2];
            #pragma unroll
            for (int p = 0; p < 4; ++p)
                ldsm_x4(bfr[2 * p][0], bfr[2 * p][1], bfr[2 * p + 1][0], bfr[2 * p + 1][1],
                        bAddr[p] + soB + ks * 32u);
            #pragma unroll
            for (int mt = 0; mt < 4; ++mt)
                #pragma unroll
                for (int nt = 0; nt < 8; ++nt)
                    mma_f16(acc[mt][nt], afr[mt], bfr[nt]);
        }
        __syncthreads();
        if (kt + 2 < NKT) stageLoad(kt + 2);
        else cp_commit();   // keep wait_group accounting valid
    }

    // epilogue
    #pragma unroll
    for (int mt = 0; mt < 4; ++mt) {
        int r0 = bM * 256 + wm * 64 + mt * 16 + g8;
        #pragma unroll
        for (int nt = 0; nt < 8; ++nt) {
            int col  = bN * 128 + wn * 64 + nt * 8 + qid * 2;
            int colL = wn * 64 + nt * 8 + qid * 2;
            if (MODE == 0) {
                float b0 = sBias[colL];
                float b1 = sBias[colL + 1];
                float x0 = acc[mt][nt][0] + b0;
                float x1 = acc[mt][nt][1] + b1;
                float x2 = acc[mt][nt][2] + b0;
                float x3 = acc[mt][nt][3] + b1;
                if (g8 == 0) {   // rows%8==0 are t==0: relu + fp16 h0
                    x0 = fmaxf(x0, 0.f); x1 = fmaxf(x1, 0.f);
                    x2 = fmaxf(x2, 0.f); x3 = fmaxf(x3, 0.f);
                    *(__half2*)(Hout + (size_t)r0 * ldH + col)       = __floats2half2_rn(x0, x1);
                    *(__half2*)(Hout + (size_t)(r0 + 8) * ldH + col) = __floats2half2_rn(x2, x3);
                }
                *(float2*)(C + (size_t)r0 * LDC + col)       = make_float2(x0, x1);
                *(float2*)(C + (size_t)(r0 + 8) * LDC + col) = make_float2(x2, x3);
            } else {
                float* p0 = C + (size_t)r0 * LDC + col;
                float* p1 = C + (size_t)(r0 + 8) * LDC + col;
                float2 g0 = *(float2*)p0;
                float2 g1 = *(float2*)p1;
                float x0 = fmaxf(acc[mt][nt][0] + g0.x, 0.f);
                float x1 = fmaxf(acc[mt][nt][1] + g0.y, 0.f);
                float x2 = fmaxf(acc[mt][nt][2] + g1.x, 0.f);
                float x3 = fmaxf(acc[mt][nt][3] + g1.y, 0.f);
                *(float2*)p0 = make_float2(x0, x1);
                *(float2*)p1 = make_float2(x2, x3);
                *(__half2*)(Hout + (size_t)r0 * ldH + col)       = __floats2half2_rn(x0, x1);
                *(__half2*)(Hout + (size_t)(r0 + 8) * ldH + col) = __floats2half2_rn(x2, x3);
            }
        }
    }
}

// pack two fp32 sources (widths 512 and 1024) into one fp16 row of 1536
template<int DST>  // 0 -> g_A16, 1 -> g_W16
__global__ void pack16(const float* __restrict__ s0, const float* __restrict__ s1, int rows)
{
    __half* dst = DST ? g_W16 : g_A16;
    size_t cid = (size_t)blockIdx.x * 256 + threadIdx.x;   // 8 cols each
    if (cid >= (size_t)rows * 192) return;
    int row = (int)(cid / 192);
    int c8  = (int)(cid % 192) * 8;
    const float* p = (c8 < 512) ? (s0 + (size_t)row * 512 + c8)
                                : (s1 + (size_t)row * 1024 + (c8 - 512));
    float4 v0 = ((const float4*)p)[0];
    float4 v1 = ((const float4*)p)[1];
    __half2 h0 = __floats2half2_rn(v0.x, v0.y);
    __half2 h1 = __floats2half2_rn(v0.z, v0.w);
    __half2 h2 = __floats2half2_rn(v1.x, v1.y);
    __half2 h3 = __floats2half2_rn(v1.z, v1.w);
    uint4 o = make_uint4(*(unsigned*)&h0, *(unsigned*)&h1, *(unsigned*)&h2, *(unsigned*)&h3);
    *(uint4*)(dst + (size_t)row * 1536 + c8) = o;
}

__global__ void cvt16(const float* __restrict__ src, int n)   // -> g_Wh16
{
    size_t i = ((size_t)blockIdx.x * 256 + threadIdx.x) * 8;
    if (i >= (size_t)n) return;
    float4 v0 = ((const float4*)(src + i))[0];
    float4 v1 = ((const float4*)(src + i))[1];
    __half2 h0 = __floats2half2_rn(v0.x, v0.y);
    __half2 h1 = __floats2half2_rn(v0.z, v0.w);
    __half2 h2 = __floats2half2_rn(v1.x, v1.y);
    __half2 h3 = __floats2half2_rn(v1.z, v1.w);
    *(uint4*)(g_Wh16 + i) = make_uint4(*(unsigned*)&h0, *(unsigned*)&h1,
                                       *(unsigned*)&h2, *(unsigned*)&h3);
}

// need[h, b] = out[b, 7, h]
__global__ void transpose_k(const float* __restrict__ out, float* __restrict__ need)
{
    __shared__ float tile[32][33];
    int h0 = blockIdx.x * 32;
    int b0 = blockIdx.y * 32;
    int x = threadIdx.x;
    int y = threadIdx.y;
    #pragma unroll
    for (int j = 0; j < 32; j += 8)
        tile[y + j][x] = out[(size_t)(b0 + y + j) * 8192 + 7168 + h0 + x];
    __syncthreads();
    #pragma unroll
    for (int j = 0; j < 32; j += 8)
        need[(size_t)(h0 + y + j) * 8192 + b0 + x] = tile[x][y + j];
}

extern "C" void kernel_launch(void* const* d_in, const int* in_sizes, int n_in,
                              void* d_out, int out_size)
{
    const float* entity   = (const float*)d_in[0];
    const float* relation = (const float*)d_in[1];
    const float* We       = (const float*)d_in[2];
    const float* be       = (const float*)d_in[3];
    const float* Wr       = (const float*)d_in[4];
    const float* br       = (const float*)d_in[5];
    const float* Wh       = (const float*)d_in[6];
    const float* bh       = (const float*)d_in[7];

    float* out  = (float*)d_out;               // [65536, 1024]
    float* need = out + (size_t)65536 * 1024;  // [1024, 8192]

    cudaFuncSetAttribute(gemm16<0>, cudaFuncAttributeMaxDynamicSharedMemorySize, SMEM_SZ);
    cudaFuncSetAttribute(gemm16<1>, cudaFuncAttributeMaxDynamicSharedMemorySize, SMEM_SZ);

    // prepass: fp16 conversions
    pack16<0><<<(int)(((size_t)65536 * 192 + 255) / 256), 256>>>(entity, relation, 65536);
    pack16<1><<<(1024 * 192 + 255) / 256, 256>>>(We, Wr, 1024);
    cvt16<<<(1024 * 1024 / 8 + 255) / 256, 256>>>(Wh, 1024 * 1024);

    // projection: M tiles = 256, N tiles = 8 (bN fastest -> A-block L2 reuse)
    gemm16<0><<<dim3(8, 256), 256, SMEM_SZ>>>(0, be, br, bh, out);

    // recurrence: M tiles = 32, N tiles = 8
    for (int t = 1; t < 8; ++t)
        gemm16<1><<<dim3(8, 32), 256, SMEM_SZ>>>(t, nullptr, nullptr, nullptr,
                                                 out + (size_t)t * 1024);

    transpose_k<<<dim3(32, 256), dim3(32, 8)>>>(out, need);
}

// round 9
// speedup vs baseline: 2.3450x; 1.2196x over previous
#include <cuda_runtime.h>
#include <cuda_fp16.h>
#include <cstdint>

// RNNModel: g = [E|R]@[We|Wr]^T + (be+br+bh)  (proj, relu on t==0 rows)
//           h_t = relu(g_t + h_{t-1}@Wh^T)    (7 in-place GEMM launches)
//           need = h_7^T
// R8: fragment double-buffering (LDSM ks+1 under MMA ks) + single barrier per
//     K-tile (mid-tile wait, next-tile frag prefetch under last MMA burst).
//     CTA tile 256x128, warp tile 64x64, fp16 gmem operands, 3-stage cp.async.
// NOTE: tcgen05 unusable in this harness build (ptxas targets compute_103 base).

#define STAGES    3
#define SROWB     144                   // bytes per smem row (64 halfs + pad)
#define A_STAGE_B (256 * SROWB)         // 36864
#define B_STAGE_B (128 * SROWB)         // 18432
#define A_REGION  (STAGES * A_STAGE_B)  // 110592
#define SMEM_SZ   (A_REGION + STAGES * B_STAGE_B + 512)   // 166400

// fp16 scratch (device-global: allocation-free)
__device__ __half g_A16[(size_t)65536 * 1536];   // packed [E|R]
__device__ __half g_W16[1024 * 1536];            // packed [We|Wr]
__device__ __half g_Wh16[1024 * 1024];
__device__ __half g_H16[(size_t)65536 * 1024];   // h_t fp16, same row indexing as out

__device__ __forceinline__ void mma_f16(float c[4], const unsigned a[4], const unsigned b[2]) {
    asm volatile(
        "mma.sync.aligned.m16n8k16.row.col.f32.f16.f16.f32 "
        "{%0,%1,%2,%3}, {%4,%5,%6,%7}, {%8,%9}, {%0,%1,%2,%3};\n"
        : "+f"(c[0]), "+f"(c[1]), "+f"(c[2]), "+f"(c[3])
        : "r"(a[0]), "r"(a[1]), "r"(a[2]), "r"(a[3]),
          "r"(b[0]), "r"(b[1]));
}
__device__ __forceinline__ void ldsm_x4(unsigned& r0, unsigned& r1, unsigned& r2, unsigned& r3,
                                        unsigned addr) {
    asm volatile("ldmatrix.sync.aligned.m8n8.x4.shared.b16 {%0,%1,%2,%3}, [%4];\n"
                 : "=r"(r0), "=r"(r1), "=r"(r2), "=r"(r3)
                 : "r"(addr));
}
__device__ __forceinline__ void cp16(unsigned dst, const void* src) {
    asm volatile("cp.async.cg.shared.global [%0], [%1], 16;" :: "r"(dst), "l"(src));
}
__device__ __forceinline__ void cp_commit() {
    asm volatile("cp.async.commit_group;" ::: "memory");
}
__device__ __forceinline__ void cp_wait0() {
    asm volatile("cp.async.wait_group 0;" ::: "memory");
}
__device__ __forceinline__ void cp_wait1() {
    asm volatile("cp.async.wait_group 1;" ::: "memory");
}

// MODE 0: C[65536,1024] = A16 @ W16^T + bias; relu + H16 write on rows%8==0.
// MODE 1: C(+t*1024 by host) = relu(C + H16(t-1) @ Wh16^T); writes H16(t).
template<int MODE>
__global__ __launch_bounds__(256, 1)
void gemm16(int t, const float* __restrict__ be, const float* __restrict__ br,
            const float* __restrict__ bhp, float* C)
{
    constexpr int KTOT = MODE ? 1024 : 1536;
    constexpr int NKT  = KTOT / 64;
    constexpr int LDA  = MODE ? 8192 : 1536;
    constexpr int LDB  = MODE ? 1024 : 1536;
    constexpr int LDC  = MODE ? 8192 : 1024;

    extern __shared__ __align__(16) char sm[];
    float* sBias = (float*)(sm + A_REGION + STAGES * B_STAGE_B);
    const unsigned smBase = (unsigned)__cvta_generic_to_shared(sm);

    const int tid = threadIdx.x;
    const int bN  = blockIdx.x;
    const int bM  = blockIdx.y;

    const __half* A = MODE ? g_H16 + (size_t)(t - 1) * 1024 : g_A16;
    const __half* B = MODE ? g_Wh16 : g_W16;
    __half* Hout = MODE ? g_H16 + (size_t)t * 1024 : g_H16;
    const int ldH = MODE ? 8192 : 1024;

    if (MODE == 0) {
        if (tid < 128) {
            int c = bN * 128 + tid;
            sBias[tid] = be[c] + br[c] + bhp[c];
        }
    }

    const int lane = tid & 31;
    const int warp = tid >> 5;
    const int wm = warp & 3;      // 4 M-warps of 64 rows
    const int wn = warp >> 2;     // 2 N-warps of 64 cols
    const int g8  = lane >> 2;    // 0..7
    const int qid = lane & 3;

    auto stageLoad = [&](int kt) {
        const int st = kt % STAGES;
        const unsigned dA = smBase + st * A_STAGE_B;
        const unsigned dB = smBase + A_REGION + st * B_STAGE_B;
        const int gk0 = kt * 64;
        #pragma unroll
        for (int i = 0; i < 8; ++i) {
            int c = tid + i * 256;
            int row = c >> 3, ch = c & 7;
            cp16(dA + row * SROWB + ch * 16,
                 A + (size_t)(bM * 256 + row) * LDA + gk0 + ch * 8);
        }
        #pragma unroll
        for (int i = 0; i < 4; ++i) {
            int c = tid + i * 256;
            int row = c >> 3, ch = c & 7;
            cp16(dB + row * SROWB + ch * 16,
                 B + (size_t)(bN * 128 + row) * LDB + gk0 + ch * 8);
        }
        cp_commit();
    };

    // ldmatrix base addresses (stage 0)
    const int rA = wm * 64 + (lane & 7) + ((lane >> 3) & 1) * 8;
    const int kselA = (lane >> 4) & 1;
    unsigned aAddr[4];
    #pragma unroll
    for (int mt = 0; mt < 4; ++mt)
        aAddr[mt] = smBase + (unsigned)((rA + mt * 16) * SROWB + kselA * 16);
    const int rB = wn * 64 + (lane & 7) + ((lane >> 4) & 1) * 8;
    const int kselB = (lane >> 3) & 1;
    unsigned bAddr[4];
    #pragma unroll
    for (int p = 0; p < 4; ++p)
        bAddr[p] = smBase + (unsigned)(A_REGION + (rB + p * 16) * SROWB + kselB * 16);

    // fragment double buffer
    unsigned af0[4][4], af1[4][4], bf0[8][2], bf1[8][2];

    auto ldF = [&](unsigned (&af)[4][4], unsigned (&bf)[8][2], unsigned offA, unsigned offB) {
        #pragma unroll
        for (int mt = 0; mt < 4; ++mt)
            ldsm_x4(af[mt][0], af[mt][1], af[mt][2], af[mt][3], aAddr[mt] + offA);
        #pragma unroll
        for (int p = 0; p < 4; ++p)
            ldsm_x4(bf[2 * p][0], bf[2 * p][1], bf[2 * p + 1][0], bf[2 * p + 1][1],
                    bAddr[p] + offB);
    };

    float acc[4][8][4];
    #pragma unroll
    for (int mt = 0; mt < 4; ++mt)
        #pragma unroll
        for (int nt = 0; nt < 8; ++nt)
            #pragma unroll
            for (int j = 0; j < 4; ++j) acc[mt][nt][j] = 0.f;

    auto mmaF = [&](unsigned (&af)[4][4], unsigned (&bf)[8][2]) {
        #pragma unroll
        for (int mt = 0; mt < 4; ++mt)
            #pragma unroll
            for (int nt = 0; nt < 8; ++nt)
                mma_f16(acc[mt][nt], af[mt], bf[nt]);
    };

    // prologue: stages 0,1 in flight; stage 0 ready; prime f0 with (0, ks0)
    stageLoad(0); stageLoad(1);
    cp_wait1();
    __syncthreads();
    ldF(af0, bf0, 0u, 0u);

    for (int kt = 0; kt < NKT; ++kt) {
        const unsigned soA = (unsigned)((kt % STAGES) * A_STAGE_B);
        const unsigned soB = (unsigned)((kt % STAGES) * B_STAGE_B);

        ldF(af1, bf1, soA + 32u, soB + 32u);          // ks1
        mmaF(af0, bf0);                               // ks0
        ldF(af0, bf0, soA + 64u, soB + 64u);          // ks2
        mmaF(af1, bf1);                               // ks1
        ldF(af1, bf1, soA + 96u, soB + 96u);          // ks3
        mmaF(af0, bf0);                               // ks2

        cp_wait0();          // stage kt+1 landed (this thread's groups)
        __syncthreads();     // visible CTA-wide; stage (kt+2)%3 free for overwrite

        if (kt + 2 < NKT) stageLoad(kt + 2);
        if (kt + 1 < NKT) {
            const unsigned nA = (unsigned)(((kt + 1) % STAGES) * A_STAGE_B);
            const unsigned nB = (unsigned)(((kt + 1) % STAGES) * B_STAGE_B);
            ldF(af0, bf0, nA, nB);                    // next tile ks0
        }
        mmaF(af1, bf1);                               // ks3
    }

    // epilogue
    #pragma unroll
    for (int mt = 0; mt < 4; ++mt) {
        int r0 = bM * 256 + wm * 64 + mt * 16 + g8;
        #pragma unroll
        for (int nt = 0; nt < 8; ++nt) {
            int col  = bN * 128 + wn * 64 + nt * 8 + qid * 2;
            int colL = wn * 64 + nt * 8 + qid * 2;
            if (MODE == 0) {
                float b0 = sBias[colL];
                float b1 = sBias[colL + 1];
                float x0 = acc[mt][nt][0] + b0;
                float x1 = acc[mt][nt][1] + b1;
                float x2 = acc[mt][nt][2] + b0;
                float x3 = acc[mt][nt][3] + b1;
                if (g8 == 0) {   // rows%8==0 are t==0: relu + fp16 h0
                    x0 = fmaxf(x0, 0.f); x1 = fmaxf(x1, 0.f);
                    x2 = fmaxf(x2, 0.f); x3 = fmaxf(x3, 0.f);
                    *(__half2*)(Hout + (size_t)r0 * ldH + col)       = __floats2half2_rn(x0, x1);
                    *(__half2*)(Hout + (size_t)(r0 + 8) * ldH + col) = __floats2half2_rn(x2, x3);
                }
                *(float2*)(C + (size_t)r0 * LDC + col)       = make_float2(x0, x1);
                *(float2*)(C + (size_t)(r0 + 8) * LDC + col) = make_float2(x2, x3);
            } else {
                float* p0 = C + (size_t)r0 * LDC + col;
                float* p1 = C + (size_t)(r0 + 8) * LDC + col;
                float2 g0 = *(float2*)p0;
                float2 g1 = *(float2*)p1;
                float x0 = fmaxf(acc[mt][nt][0] + g0.x, 0.f);
                float x1 = fmaxf(acc[mt][nt][1] + g0.y, 0.f);
                float x2 = fmaxf(acc[mt][nt][2] + g1.x, 0.f);
                float x3 = fmaxf(acc[mt][nt][3] + g1.y, 0.f);
                *(float2*)p0 = make_float2(x0, x1);
                *(float2*)p1 = make_float2(x2, x3);
                *(__half2*)(Hout + (size_t)r0 * ldH + col)       = __floats2half2_rn(x0, x1);
                *(__half2*)(Hout + (size_t)(r0 + 8) * ldH + col) = __floats2half2_rn(x2, x3);
            }
        }
    }
}

// pack two fp32 sources (widths 512 and 1024) into one fp16 row of 1536
template<int DST>  // 0 -> g_A16, 1 -> g_W16
__global__ void pack16(const float* __restrict__ s0, const float* __restrict__ s1, int rows)
{
    __half* dst = DST ? g_W16 : g_A16;
    size_t cid = (size_t)blockIdx.x * 256 + threadIdx.x;   // 8 cols each
    if (cid >= (size_t)rows * 192) return;
    int row = (int)(cid / 192);
    int c8  = (int)(cid % 192) * 8;
    const float* p = (c8 < 512) ? (s0 + (size_t)row * 512 + c8)
                                : (s1 + (size_t)row * 1024 + (c8 - 512));
    float4 v0 = ((const float4*)p)[0];
    float4 v1 = ((const float4*)p)[1];
    __half2 h0 = __floats2half2_rn(v0.x, v0.y);
    __half2 h1 = __floats2half2_rn(v0.z, v0.w);
    __half2 h2 = __floats2half2_rn(v1.x, v1.y);
    __half2 h3 = __floats2half2_rn(v1.z, v1.w);
    uint4 o = make_uint4(*(unsigned*)&h0, *(unsigned*)&h1, *(unsigned*)&h2, *(unsigned*)&h3);
    *(uint4*)(dst + (size_t)row * 1536 + c8) = o;
}

__global__ void cvt16(const float* __restrict__ src, int n)   // -> g_Wh16
{
    size_t i = ((size_t)blockIdx.x * 256 + threadIdx.x) * 8;
    if (i >= (size_t)n) return;
    float4 v0 = ((const float4*)(src + i))[0];
    float4 v1 = ((const float4*)(src + i))[1];
    __half2 h0 = __floats2half2_rn(v0.x, v0.y);
    __half2 h1 = __floats2half2_rn(v0.z, v0.w);
    __half2 h2 = __floats2half2_rn(v1.x, v1.y);
    __half2 h3 = __floats2half2_rn(v1.z, v1.w);
    *(uint4*)(g_Wh16 + i) = make_uint4(*(unsigned*)&h0, *(unsigned*)&h1,
                                       *(unsigned*)&h2, *(unsigned*)&h3);
}

// need[h, b] = out[b, 7, h]
__global__ void transpose_k(const float* __restrict__ out, float* __restrict__ need)
{
    __shared__ float tile[32][33];
    int h0 = blockIdx.x * 32;
    int b0 = blockIdx.y * 32;
    int x = threadIdx.x;
    int y = threadIdx.y;
    #pragma unroll
    for (int j = 0; j < 32; j += 8)
        tile[y + j][x] = out[(size_t)(b0 + y + j) * 8192 + 7168 + h0 + x];
    __syncthreads();
    #pragma unroll
    for (int j = 0; j < 32; j += 8)
        need[(size_t)(h0 + y + j) * 8192 + b0 + x] = tile[x][y + j];
}

extern "C" void kernel_launch(void* const* d_in, const int* in_sizes, int n_in,
                              void* d_out, int out_size)
{
    const float* entity   = (const float*)d_in[0];
    const float* relation = (const float*)d_in[1];
    const float* We       = (const float*)d_in[2];
    const float* be       = (const float*)d_in[3];
    const float* Wr       = (const float*)d_in[4];
    const float* br       = (const float*)d_in[5];
    const float* Wh       = (const float*)d_in[6];
    const float* bh       = (const float*)d_in[7];

    float* out  = (float*)d_out;               // [65536, 1024]
    float* need = out + (size_t)65536 * 1024;  // [1024, 8192]

    cudaFuncSetAttribute(gemm16<0>, cudaFuncAttributeMaxDynamicSharedMemorySize, SMEM_SZ);
    cudaFuncSetAttribute(gemm16<1>, cudaFuncAttributeMaxDynamicSharedMemorySize, SMEM_SZ);

    // prepass: fp16 conversions
    pack16<0><<<(int)(((size_t)65536 * 192 + 255) / 256), 256>>>(entity, relation, 65536);
    pack16<1><<<(1024 * 192 + 255) / 256, 256>>>(We, Wr, 1024);
    cvt16<<<(1024 * 1024 / 8 + 255) / 256, 256>>>(Wh, 1024 * 1024);

    // projection: M tiles = 256, N tiles = 8 (bN fastest -> A-block L2 reuse)
    gemm16<0><<<dim3(8, 256), 256, SMEM_SZ>>>(0, be, br, bh, out);

    // recurrence: M tiles = 32, N tiles = 8
    for (int t = 1; t < 8; ++t)
        gemm16<1><<<dim3(8, 32), 256, SMEM_SZ>>>(t, nullptr, nullptr, nullptr,
                                                 out + (size_t)t * 1024);

    transpose_k<<<dim3(32, 256), dim3(32, 8)>>>(out, need);
}